// round 1
// baseline (speedup 1.0000x reference)
#include <cuda_runtime.h>
#include <cuda_bf16.h>
#include <cstdint>

// Soft decision tree inference, DEPTH=8, 32 feats, 10 classes, B=131072.
// P(leaf) = (prod e over right edges) / (prod (1+e) over path), e = exp(x[f]-t).
// DFS over leaves with N/D prefixes; one RCP per depth-7 node (shared by leaf pair).

#define DEPTH   8
#define N_FEAT  32
#define N_CLS   10
#define BT      256               // block threads
#define N_INT   255               // internal nodes
#define N_LEAF  256

#define LOG2E 1.4426950408889634f

// params: .x = -t*log2e, .y = bitcast(int f*BT)  (element offset into xs for this node's feature)
__constant__ float2 c_p[N_INT];
__constant__ int    c_cls[N_LEAF];

__device__ float2 g_p[N_INT];     // prep scratch (no allocs allowed)

__global__ void prep_kernel(const float* __restrict__ thr, const int* __restrict__ feats) {
    int i = threadIdx.x;
    if (i < N_INT) {
        g_p[i] = make_float2(-thr[i] * LOG2E, __int_as_float(feats[i] * BT));
    }
}

// 10 separate named accumulators (NOT an array) so the uniform-class switch
// cannot be turned into a dynamically-indexed local-memory store.
struct Acc {
    float a0, a1, a2, a3, a4, a5, a6, a7, a8, a9;
};

__device__ __forceinline__ void accum(Acc& A, int c, float p) {
    switch (c) {
        case 0: A.a0 += p; break;
        case 1: A.a1 += p; break;
        case 2: A.a2 += p; break;
        case 3: A.a3 += p; break;
        case 4: A.a4 += p; break;
        case 5: A.a5 += p; break;
        case 6: A.a6 += p; break;
        case 7: A.a7 += p; break;
        case 8: A.a8 += p; break;
        case 9: A.a9 += p; break;
        default: break;
    }
}

__device__ __forceinline__ float ex2f(float z) {
    float e;
    asm("ex2.approx.f32 %0, %1;" : "=f"(e) : "f"(z));
    return e;
}
__device__ __forceinline__ float rcpf(float d) {
    float r;
    asm("rcp.approx.f32 %0, %1;" : "=f"(r) : "f"(d));
    return r;
}

// Fully unrolled DFS. d = depth (0..7), node = in-level index. All node
// indices are compile-time constants -> constant-bank loads with immediate
// offsets, all index math folded away.
template <int d, int node>
struct Walk {
    static __device__ __forceinline__ void run(float N, float D,
                                               const float* __restrict__ xt, Acc& A) {
        constexpr int g = (1 << d) - 1 + node;
        float2 p = c_p[g];
        float z = fmaf(xt[__float_as_int(p.y)], LOG2E, p.x);
        float e = ex2f(z);                 // e = exp(x[f]-t)
        float Dn = fmaf(D, e, D);          // D * (1+e)
        Walk<d + 1, 2 * node>::run(N, Dn, xt, A);        // left: numerator unchanged
        Walk<d + 1, 2 * node + 1>::run(N * e, Dn, xt, A); // right: numerator *= e
    }
};

// depth 7: one RCP serves both leaves of this node.
template <int node>
struct Walk<DEPTH - 1, node> {
    static __device__ __forceinline__ void run(float N, float D,
                                               const float* __restrict__ xt, Acc& A) {
        constexpr int g = (1 << (DEPTH - 1)) - 1 + node;
        float2 p = c_p[g];
        float z = fmaf(xt[__float_as_int(p.y)], LOG2E, p.x);
        float e = ex2f(z);
        float Dn = fmaf(D, e, D);
        float r  = rcpf(Dn);
        float Pl = N * r;                  // leaf 2*node   (left)
        float Pr = Pl * e;                 // leaf 2*node+1 (right)
        accum(A, c_cls[2 * node],     Pl);
        accum(A, c_cls[2 * node + 1], Pr);
    }
};

__global__ void __launch_bounds__(BT, 4)
dt_kernel(const float* __restrict__ x, float* __restrict__ out) {
    __shared__ float xs[N_FEAT * BT];      // transposed: xs[f*BT + tid], conflict-free

    const int tid = threadIdx.x;
    const int bs  = blockIdx.x * BT;

    // Stage this block's 256 x-rows transposed into shared. Each thread reads
    // its own contiguous 128B row (warp covers 4KB contiguous).
    const float4* xr = reinterpret_cast<const float4*>(x + (size_t)(bs + tid) * N_FEAT);
#pragma unroll
    for (int i = 0; i < N_FEAT / 4; i++) {
        float4 v = xr[i];
        xs[(4 * i + 0) * BT + tid] = v.x;
        xs[(4 * i + 1) * BT + tid] = v.y;
        xs[(4 * i + 2) * BT + tid] = v.z;
        xs[(4 * i + 3) * BT + tid] = v.w;
    }
    __syncthreads();

    Acc A = {0.f, 0.f, 0.f, 0.f, 0.f, 0.f, 0.f, 0.f, 0.f, 0.f};

    Walk<0, 0>::run(1.0f, 1.0f, xs + tid, A);

    float* o = out + (size_t)(bs + tid) * N_CLS;
    o[0] = A.a0; o[1] = A.a1; o[2] = A.a2; o[3] = A.a3; o[4] = A.a4;
    o[5] = A.a5; o[6] = A.a6; o[7] = A.a7; o[8] = A.a8; o[9] = A.a9;
}

extern "C" void kernel_launch(void* const* d_in, const int* in_sizes, int n_in,
                              void* d_out, int out_size) {
    const float* x     = (const float*)d_in[0];
    const float* thr   = (const float*)d_in[1];
    const int*   feats = (const int*)d_in[2];
    const int*   cls   = (const int*)d_in[3];
    float*       out   = (float*)d_out;

    const int B = in_sizes[0] / N_FEAT;

    prep_kernel<<<1, 256>>>(thr, feats);

    void* gp = nullptr;
    cudaGetSymbolAddress(&gp, g_p);
    cudaMemcpyToSymbolAsync(c_p, gp, sizeof(float2) * N_INT, 0,
                            cudaMemcpyDeviceToDevice, 0);
    cudaMemcpyToSymbolAsync(c_cls, cls, sizeof(int) * N_LEAF, 0,
                            cudaMemcpyDeviceToDevice, 0);

    dt_kernel<<<B / BT, BT>>>(x, out);
}

// round 2
// speedup vs baseline: 1.9923x; 1.9923x over previous
#include <cuda_runtime.h>
#include <cuda_bf16.h>
#include <cstdint>

// Soft decision tree, DEPTH=8, 32 feats, 10 classes, B=131072.
// P(leaf) = (prod e over right edges) / (prod (1+e) over path), e = exp(x[f]-t).
// Fully unrolled DFS; branchless leaf accumulation into per-thread shared columns.

#define DEPTH   8
#define N_FEAT  32
#define N_CLS   10
#define BT      256
#define N_INT   255
#define N_LEAF  256
#define N_D7    128               // depth-7 internal nodes

#define LOG2E 1.4426950408889634f

// per internal node: .x = -t*log2e, .y = bitcast(f * BT * 4)  (byte offset into xs)
__constant__ float2   c_p[N_INT];
// per depth-7 node: packed byte offsets (cls_left*BT*4) | (cls_right*BT*4 << 16)
__constant__ uint32_t c_pk[N_D7];

__device__ float2   g_p[N_INT];
__device__ uint32_t g_pk[N_D7];

__global__ void prep_kernel(const float* __restrict__ thr,
                            const int*   __restrict__ feats,
                            const int*   __restrict__ cls) {
    int i = threadIdx.x;
    if (i < N_INT) {
        g_p[i] = make_float2(-thr[i] * LOG2E, __int_as_float(feats[i] * BT * 4));
    }
    if (i < N_D7) {
        uint32_t offL = (uint32_t)cls[2 * i]     * (BT * 4);
        uint32_t offR = (uint32_t)cls[2 * i + 1] * (BT * 4);
        g_pk[i] = offL | (offR << 16);
    }
}

__device__ __forceinline__ float ex2f(float z) {
    float e; asm("ex2.approx.f32 %0, %1;" : "=f"(e) : "f"(z)); return e;
}
__device__ __forceinline__ float rcpf(float d) {
    float r; asm("rcp.approx.f32 %0, %1;" : "=f"(r) : "f"(d)); return r;
}

// xb = (char*)xs + tid*4 ; sb = (char*)sacc + tid*4
template <int d, int node>
struct Walk {
    static __device__ __forceinline__ void run(float N, float D,
                                               const char* xb, char* sb) {
        constexpr int g = (1 << d) - 1 + node;
        float2 p = c_p[g];
        float xv = *(const float*)(xb + __float_as_int(p.y));
        float z  = fmaf(xv, LOG2E, p.x);
        float e  = ex2f(z);                // exp(x[f]-t)
        float Dn = fmaf(D, e, D);          // D*(1+e)
        Walk<d + 1, 2 * node>::run(N, Dn, xb, sb);
        Walk<d + 1, 2 * node + 1>::run(N * e, Dn, xb, sb);
    }
};

template <int node>
struct Walk<DEPTH - 1, node> {
    static __device__ __forceinline__ void run(float N, float D,
                                               const char* xb, char* sb) {
        constexpr int g = (1 << (DEPTH - 1)) - 1 + node;
        float2 p = c_p[g];
        float xv = *(const float*)(xb + __float_as_int(p.y));
        float z  = fmaf(xv, LOG2E, p.x);
        float e  = ex2f(z);
        float Dn = fmaf(D, e, D);
        float r  = rcpf(Dn);
        float Pl = N * r;                  // left leaf prob
        float Pr = Pl * e;                 // right leaf prob
        uint32_t pk   = c_pk[node];
        float* aL = (float*)(sb + (pk & 0xFFFFu));
        float* aR = (float*)(sb + (pk >> 16));
        *aL += Pl;                         // LDS+FADD+STS, branch-free
        *aR += Pr;
    }
};

__global__ void __launch_bounds__(BT, 4)
dt_kernel(const float* __restrict__ x, float* __restrict__ out) {
    __shared__ float xs[N_FEAT * BT];   // 32 KB, xs[f*BT + tid]
    __shared__ float sacc[N_CLS * BT];  // 10 KB, sacc[c*BT + tid]

    const int tid = threadIdx.x;
    const int bs  = blockIdx.x * BT;

    // Stage own sample's 32 features into own shared column (no sync needed:
    // each thread reads back only what it wrote).
    const float4* xr = reinterpret_cast<const float4*>(x + (size_t)(bs + tid) * N_FEAT);
#pragma unroll
    for (int i = 0; i < N_FEAT / 4; i++) {
        float4 v = xr[i];
        xs[(4 * i + 0) * BT + tid] = v.x;
        xs[(4 * i + 1) * BT + tid] = v.y;
        xs[(4 * i + 2) * BT + tid] = v.z;
        xs[(4 * i + 3) * BT + tid] = v.w;
    }
#pragma unroll
    for (int c = 0; c < N_CLS; c++) sacc[c * BT + tid] = 0.0f;

    const char* xb = (const char*)xs + tid * 4;
    char*       sb = (char*)sacc + tid * 4;

    Walk<0, 0>::run(1.0f, 1.0f, xb, sb);

    float* o = out + (size_t)(bs + tid) * N_CLS;
#pragma unroll
    for (int c = 0; c < N_CLS; c++) o[c] = sacc[c * BT + tid];
}

extern "C" void kernel_launch(void* const* d_in, const int* in_sizes, int n_in,
                              void* d_out, int out_size) {
    const float* x     = (const float*)d_in[0];
    const float* thr   = (const float*)d_in[1];
    const int*   feats = (const int*)d_in[2];
    const int*   cls   = (const int*)d_in[3];
    float*       out   = (float*)d_out;

    const int B = in_sizes[0] / N_FEAT;

    prep_kernel<<<1, 256>>>(thr, feats, cls);

    void* gp = nullptr; void* gk = nullptr;
    cudaGetSymbolAddress(&gp, g_p);
    cudaGetSymbolAddress(&gk, g_pk);
    cudaMemcpyToSymbolAsync(c_p,  gp, sizeof(float2)   * N_INT, 0,
                            cudaMemcpyDeviceToDevice, 0);
    cudaMemcpyToSymbolAsync(c_pk, gk, sizeof(uint32_t) * N_D7, 0,
                            cudaMemcpyDeviceToDevice, 0);

    dt_kernel<<<B / BT, BT>>>(x, out);
}

// round 4
// speedup vs baseline: 2.2926x; 1.1507x over previous
#include <cuda_runtime.h>
#include <cuda_bf16.h>
#include <cstdint>

// Soft decision tree, DEPTH=8, 32 feats, 10 classes, B=131072.
// P(leaf) = (prod e over right edges) / (prod (1+e) over path), e = exp(x[f]-t).
// Fully unrolled DFS; 2 samples per thread (paired columns, LDS.64/STS.64);
// branchless leaf accumulation into per-thread shared column pairs.

#define DEPTH   8
#define N_FEAT  32
#define N_CLS   10
#define BT      128               // threads per block
#define SPB     256               // samples per block (2 per thread)
#define PADF    258               // padded floats per feature row (bank-conflict-free)
#define N_INT   255
#define N_D7    128

#define LOG2E 1.4426950408889634f

// per internal node: .x = -t*log2e, .y = bitcast(f * PADF * 4) byte offset
__constant__ float2   c_p[N_INT];
// per depth-7 node: (clsL*SPB*4) | (clsR*SPB*4 << 16)   byte offsets into sacc
__constant__ uint32_t c_pk[N_D7];

__device__ float2   g_p[N_INT];
__device__ uint32_t g_pk[N_D7];

__global__ void prep_kernel(const float* __restrict__ thr,
                            const int*   __restrict__ feats,
                            const int*   __restrict__ cls) {
    int i = threadIdx.x;
    if (i < N_INT) {
        g_p[i] = make_float2(-thr[i] * LOG2E, __int_as_float(feats[i] * PADF * 4));
    }
    if (i < N_D7) {
        uint32_t offL = (uint32_t)cls[2 * i]     * (SPB * 4);
        uint32_t offR = (uint32_t)cls[2 * i + 1] * (SPB * 4);
        g_pk[i] = offL | (offR << 16);
    }
}

__device__ __forceinline__ float ex2f(float z) {
    float e; asm("ex2.approx.f32 %0, %1;" : "=f"(e) : "f"(z)); return e;
}
__device__ __forceinline__ float rcpf(float d) {
    float r; asm("rcp.approx.f32 %0, %1;" : "=f"(r) : "f"(d)); return r;
}

// xb = (char*)xs + 8*pr ; sb = (char*)sacc + 8*pr
template <int d, int node>
struct Walk {
    static __device__ __forceinline__ void run(float Na, float Da, float Nb, float Db,
                                               const char* xb, char* sb) {
        constexpr int g = (1 << d) - 1 + node;
        float2 p  = c_p[g];
        float2 xv = *(const float2*)(xb + __float_as_int(p.y));   // LDS.64: both samples
        float za = fmaf(xv.x, LOG2E, p.x);
        float zb = fmaf(xv.y, LOG2E, p.x);
        float ea = ex2f(za);
        float eb = ex2f(zb);
        float Dna = fmaf(Da, ea, Da);      // D*(1+e)
        float Dnb = fmaf(Db, eb, Db);
        Walk<d + 1, 2 * node>::run(Na, Dna, Nb, Dnb, xb, sb);
        Walk<d + 1, 2 * node + 1>::run(Na * ea, Dna, Nb * eb, Dnb, xb, sb);
    }
};

template <int node>
struct Walk<DEPTH - 1, node> {
    static __device__ __forceinline__ void run(float Na, float Da, float Nb, float Db,
                                               const char* xb, char* sb) {
        constexpr int g = (1 << (DEPTH - 1)) - 1 + node;
        float2 p  = c_p[g];
        float2 xv = *(const float2*)(xb + __float_as_int(p.y));
        float za = fmaf(xv.x, LOG2E, p.x);
        float zb = fmaf(xv.y, LOG2E, p.x);
        float ea = ex2f(za);
        float eb = ex2f(zb);
        float Dna = fmaf(Da, ea, Da);
        float Dnb = fmaf(Db, eb, Db);
        float ra = rcpf(Dna);
        float rb = rcpf(Dnb);
        float Pla = Na * ra, Plb = Nb * rb;       // left leaf, samples a/b
        float Pra = Pla * ea, Prb = Plb * eb;     // right leaf
        uint32_t pk = c_pk[node];
        float2* aL = (float2*)(sb + (pk & 0xFFFFu));
        float2* aR = (float2*)(sb + (pk >> 16));
        float2 vL = *aL; vL.x += Pla; vL.y += Plb; *aL = vL;   // LDS.64/STS.64
        float2 vR = *aR; vR.x += Pra; vR.y += Prb; *aR = vR;
    }
};

__global__ void __launch_bounds__(BT)
dt_kernel(const float* __restrict__ x, float* __restrict__ out) {
    __shared__ __align__(16) float xs[N_FEAT * PADF];   // 33 KB, xs[f*PADF + s]
    __shared__ __align__(16) float sacc[N_CLS * SPB];   // 10 KB, sacc[c*SPB + s]

    const int tid = threadIdx.x;
    const int bs  = blockIdx.x * SPB;

    // Stage 256 samples x 32 feats, fully coalesced LDG.128, conflict-free STS.
#pragma unroll
    for (int k = 0; k < (SPB * N_FEAT / 4) / BT; k++) {
        int idx = tid + k * BT;            // float4 index
        int s   = idx >> 3;                // sample
        int q   = idx & 7;                 // float4 within sample
        float4 v = reinterpret_cast<const float4*>(x + (size_t)(bs + s) * N_FEAT)[q];
        xs[(q * 4 + 0) * PADF + s] = v.x;
        xs[(q * 4 + 1) * PADF + s] = v.y;
        xs[(q * 4 + 2) * PADF + s] = v.z;
        xs[(q * 4 + 3) * PADF + s] = v.w;
    }

    char* sb = (char*)sacc + 8 * tid;      // this thread's pair of accum columns
#pragma unroll
    for (int c = 0; c < N_CLS; c++) *(float2*)(sb + c * (SPB * 4)) = make_float2(0.f, 0.f);

    __syncthreads();

    const char* xb = (const char*)xs + 8 * tid;
    Walk<0, 0>::run(1.0f, 1.0f, 1.0f, 1.0f, xb, sb);

    // Write out both samples' 10 class probs (vector stores, 16B-aligned split).
    float a[N_CLS], b[N_CLS];
#pragma unroll
    for (int c = 0; c < N_CLS; c++) {
        float2 v = *(const float2*)(sb + c * (SPB * 4));
        a[c] = v.x; b[c] = v.y;
    }
    float* o = out + (size_t)(bs + 2 * tid) * N_CLS;   // 80-byte aligned
    ((float4*)o)[0] = make_float4(a[0], a[1], a[2], a[3]);
    ((float4*)o)[1] = make_float4(a[4], a[5], a[6], a[7]);
    ((float2*)o)[4] = make_float2(a[8], a[9]);
    ((float2*)o)[5] = make_float2(b[0], b[1]);
    ((float4*)(o + 12))[0] = make_float4(b[2], b[3], b[4], b[5]);
    ((float4*)(o + 12))[1] = make_float4(b[6], b[7], b[8], b[9]);
}

extern "C" void kernel_launch(void* const* d_in, const int* in_sizes, int n_in,
                              void* d_out, int out_size) {
    const float* x     = (const float*)d_in[0];
    const float* thr   = (const float*)d_in[1];
    const int*   feats = (const int*)d_in[2];
    const int*   cls   = (const int*)d_in[3];
    float*       out   = (float*)d_out;

    const int B = in_sizes[0] / N_FEAT;

    prep_kernel<<<1, 256>>>(thr, feats, cls);

    void* gp = nullptr; void* gk = nullptr;
    cudaGetSymbolAddress(&gp, g_p);
    cudaGetSymbolAddress(&gk, g_pk);
    cudaMemcpyToSymbolAsync(c_p,  gp, sizeof(float2)   * N_INT, 0,
                            cudaMemcpyDeviceToDevice, 0);
    cudaMemcpyToSymbolAsync(c_pk, gk, sizeof(uint32_t) * N_D7, 0,
                            cudaMemcpyDeviceToDevice, 0);

    dt_kernel<<<B / SPB, BT>>>(x, out);
}

// round 6
// speedup vs baseline: 2.3842x; 1.0400x over previous
#include <cuda_runtime.h>
#include <cuda_bf16.h>
#include <cstdint>

// Soft decision tree, DEPTH=8, 32 feats, 10 classes, B=131072.
// P(leaf) = (prod e over right edges) / (prod (1+e) over path), e = exp(x[f]-t).
// 2 samples per thread (paired LDS.64) x 4-way subtree split per sample-pair:
// each thread replicates the top 2 levels, then owns one depth-2 subtree.

#define DEPTH   8
#define N_FEAT  32
#define N_CLS   10
#define BT      256               // threads per block
#define SPB     128               // samples per block (64 pairs x 4 quarter-threads)
#define NPAIR   64
#define PADF    130               // padded floats per feature row
#define N_SUB   63                // nodes per depth-2 subtree
#define N_D7Q   32                // depth-7 nodes per quarter

#define LOG2E 1.4426950408889634f

// top 2 levels: [0]=root, [1]=depth1-left, [2]=depth1-right.  .x=-t*log2e, .y=bitcast(f*PADF*4)
__constant__ float2   c_top[3];
// per-quarter repacked subtrees: c_ps[q*63 + (1<<ld)-1 + j], ld = depth-2
__constant__ float2   c_ps[4 * N_SUB];
// per-quarter depth-7 class offsets: (clsL*SPB*4) | (clsR*SPB*4 << 16)
__constant__ uint32_t c_pk[4 * N_D7Q];

__device__ float2   g_top[3];
__device__ float2   g_ps[4 * N_SUB];
__device__ uint32_t g_pk[4 * N_D7Q];

__global__ void prep_kernel(const float* __restrict__ thr,
                            const int*   __restrict__ feats,
                            const int*   __restrict__ cls) {
    int i = threadIdx.x;
    if (i < 3) {
        g_top[i] = make_float2(-thr[i] * LOG2E, __int_as_float(feats[i] * PADF * 4));
    }
    if (i < 4 * N_SUB) {
        int q   = i / N_SUB;
        int rem = i - q * N_SUB;           // 0..62 within subtree (level order)
        int ld  = 31 - __clz(rem + 1);     // 0..5 (tree depth = ld+2)
        int j   = rem + 1 - (1 << ld);
        int d   = ld + 2;
        int g   = ((1 << d) - 1) + q * (1 << ld) + j;   // global node index
        g_ps[i] = make_float2(-thr[g] * LOG2E, __int_as_float(feats[g] * PADF * 4));
    }
    if (i < 4 * N_D7Q) {                   // i == global depth-7 in-level index
        uint32_t offL = (uint32_t)cls[2 * i]     * (SPB * 4);
        uint32_t offR = (uint32_t)cls[2 * i + 1] * (SPB * 4);
        g_pk[i] = offL | (offR << 16);
    }
}

__device__ __forceinline__ float ex2f(float z) {
    float e; asm("ex2.approx.f32 %0, %1;" : "=f"(e) : "f"(z)); return e;
}
__device__ __forceinline__ float rcpf(float d) {
    float r; asm("rcp.approx.f32 %0, %1;" : "=f"(r) : "f"(d)); return r;
}

// ld = local depth in subtree (0..5), j = local node index. pbase/kbase are
// warp-uniform runtime bases (q*63 / q*32) -> LDC [UR+imm] param loads.
template <int ld, int j>
struct Walk {
    static __device__ __forceinline__ void run(float Na, float Da, float Nb, float Db,
                                               const char* xb, char* sb,
                                               int pbase, int kbase) {
        float2 p  = c_ps[pbase + (1 << ld) - 1 + j];
        float2 xv = *(const float2*)(xb + __float_as_int(p.y));   // both samples
        float ea = ex2f(fmaf(xv.x, LOG2E, p.x));
        float eb = ex2f(fmaf(xv.y, LOG2E, p.x));
        float Dna = fmaf(Da, ea, Da);      // D*(1+e)
        float Dnb = fmaf(Db, eb, Db);
        Walk<ld + 1, 2 * j>::run(Na, Dna, Nb, Dnb, xb, sb, pbase, kbase);
        Walk<ld + 1, 2 * j + 1>::run(Na * ea, Dna, Nb * eb, Dnb, xb, sb, pbase, kbase);
    }
};

template <int j>
struct Walk<5, j> {                        // depth-7 nodes: rcp + leaf accumulate
    static __device__ __forceinline__ void run(float Na, float Da, float Nb, float Db,
                                               const char* xb, char* sb,
                                               int pbase, int kbase) {
        float2 p  = c_ps[pbase + 31 + j];
        float2 xv = *(const float2*)(xb + __float_as_int(p.y));
        float ea = ex2f(fmaf(xv.x, LOG2E, p.x));
        float eb = ex2f(fmaf(xv.y, LOG2E, p.x));
        float Dna = fmaf(Da, ea, Da);
        float Dnb = fmaf(Db, eb, Db);
        float ra = rcpf(Dna);
        float rb = rcpf(Dnb);
        float Pla = Na * ra,  Plb = Nb * rb;
        float Pra = Pla * ea, Prb = Plb * eb;
        uint32_t pk = c_pk[kbase + j];
        float2* aL = (float2*)(sb + (pk & 0xFFFFu));
        float2* aR = (float2*)(sb + (pk >> 16));
        float2 vL = *aL; vL.x += Pla; vL.y += Plb; *aL = vL;
        float2 vR = *aR; vR.x += Pra; vR.y += Prb; *aR = vR;
    }
};

__global__ void __launch_bounds__(BT, 4)
dt_kernel(const float* __restrict__ x, float* __restrict__ out) {
    __shared__ __align__(16) float xs[N_FEAT * PADF];        // 16.6 KB, xs[f*PADF + s]
    __shared__ __align__(16) float sacc[4 * N_CLS * SPB];    // 20 KB, per-quarter regions

    const int tid = threadIdx.x;
    const int bs  = blockIdx.x * SPB;
    const int q   = tid >> 6;              // quarter (warp-uniform)
    const int pr  = tid & (NPAIR - 1);     // sample-pair index

    // Stage 128 samples x 32 feats: coalesced LDG.128, near-conflict-free STS.
#pragma unroll
    for (int k = 0; k < (SPB * N_FEAT / 4) / BT; k++) {
        int idx = tid + k * BT;            // float4 index
        int s   = idx >> 3;                // sample
        int c4  = idx & 7;                 // float4 within sample
        float4 v = reinterpret_cast<const float4*>(x + (size_t)(bs + s) * N_FEAT)[c4];
        xs[(c4 * 4 + 0) * PADF + s] = v.x;
        xs[(c4 * 4 + 1) * PADF + s] = v.y;
        xs[(c4 * 4 + 2) * PADF + s] = v.z;
        xs[(c4 * 4 + 3) * PADF + s] = v.w;
    }

    char* sb = (char*)sacc + q * (N_CLS * SPB * 4) + 8 * pr;
#pragma unroll
    for (int c = 0; c < N_CLS; c++)
        *(float2*)(sb + c * (SPB * 4)) = make_float2(0.f, 0.f);

    __syncthreads();

    const char* xb = (const char*)xs + 8 * pr;

    // Replicated top 2 levels (root + depth-1 ancestor of this quarter).
    float2 p0  = c_top[0];
    float2 xv0 = *(const float2*)(xb + __float_as_int(p0.y));
    float e0a = ex2f(fmaf(xv0.x, LOG2E, p0.x));
    float e0b = ex2f(fmaf(xv0.y, LOG2E, p0.x));
    float Da = fmaf(1.f, e0a, 1.f);        // 1+e0
    float Db = fmaf(1.f, e0b, 1.f);
    float Na = (q & 2) ? e0a : 1.0f;       // root right-edge?
    float Nb = (q & 2) ? e0b : 1.0f;

    float2 p1  = c_top[1 + (q >> 1)];
    float2 xv1 = *(const float2*)(xb + __float_as_int(p1.y));
    float e1a = ex2f(fmaf(xv1.x, LOG2E, p1.x));
    float e1b = ex2f(fmaf(xv1.y, LOG2E, p1.x));
    Da = fmaf(Da, e1a, Da);                // *(1+e1)
    Db = fmaf(Db, e1b, Db);
    if (q & 1) { Na *= e1a; Nb *= e1b; }   // depth-1 right-edge?

    Walk<0, 0>::run(Na, Da, Nb, Db, xb, sb, q * N_SUB, q * N_D7Q);

    __syncthreads();

    // Combine 4 quarter-accumulators and write out. Threads 0..127, sample t.
    if (tid < SPB) {
        float a[N_CLS];
#pragma unroll
        for (int c = 0; c < N_CLS; c++) {
            float v = 0.f;
#pragma unroll
            for (int qq = 0; qq < 4; qq++)
                v += sacc[qq * (N_CLS * SPB) + c * SPB + tid];
            a[c] = v;
        }
        float* o = out + (size_t)(bs + tid) * N_CLS;   // 40B stride -> 8-aligned
#pragma unroll
        for (int c = 0; c < N_CLS; c += 2)
            *(float2*)(o + c) = make_float2(a[c], a[c + 1]);
    }
}

extern "C" void kernel_launch(void* const* d_in, const int* in_sizes, int n_in,
                              void* d_out, int out_size) {
    const float* x     = (const float*)d_in[0];
    const float* thr   = (const float*)d_in[1];
    const int*   feats = (const int*)d_in[2];
    const int*   cls   = (const int*)d_in[3];
    float*       out   = (float*)d_out;

    const int B = in_sizes[0] / N_FEAT;

    prep_kernel<<<1, 256>>>(thr, feats, cls);

    void *gt = nullptr, *gp = nullptr, *gk = nullptr;
    cudaGetSymbolAddress(&gt, g_top);
    cudaGetSymbolAddress(&gp, g_ps);
    cudaGetSymbolAddress(&gk, g_pk);
    cudaMemcpyToSymbolAsync(c_top, gt, sizeof(float2) * 3, 0,
                            cudaMemcpyDeviceToDevice, 0);
    cudaMemcpyToSymbolAsync(c_ps,  gp, sizeof(float2) * 4 * N_SUB, 0,
                            cudaMemcpyDeviceToDevice, 0);
    cudaMemcpyToSymbolAsync(c_pk,  gk, sizeof(uint32_t) * 4 * N_D7Q, 0,
                            cudaMemcpyDeviceToDevice, 0);

    dt_kernel<<<B / SPB, BT>>>(x, out);
}

// round 7
// speedup vs baseline: 3.0379x; 1.2742x over previous
#include <cuda_runtime.h>
#include <cuda_bf16.h>
#include <cstdint>

// Soft decision tree, DEPTH=8, 32 feats, 10 classes, B=131072.
// P(leaf) = (prod e over right edges) / (prod (1+e) over path), e = exp(x[f]-t).
// Single fused kernel: per-block param prep in shared, 2 samples/thread,
// 4-way subtree split, pairwise-combined rcp at depth-6 (one rcp per 2 d7 nodes).

#define DEPTH   8
#define N_FEAT  32
#define N_CLS   10
#define BT      256               // threads per block
#define SPB     128               // samples per block (64 pairs x 4 quarter-threads)
#define NPAIR   64
#define PADF    130               // padded floats per feature row
#define N_SUB   63                // nodes per depth-2 subtree

#define LOG2E 1.4426950408889634f

__device__ __forceinline__ float ex2f(float z) {
    float e; asm("ex2.approx.f32 %0, %1;" : "=f"(e) : "f"(z)); return e;
}
__device__ __forceinline__ float rcpf(float d) {
    float r; asm("rcp.approx.f32 %0, %1;" : "=f"(r) : "f"(d)); return r;
}

__device__ __forceinline__ float2 lds2(const char* p) { return *(const float2*)p; }

// ld = local depth in subtree (0..4), j = local node index.
// ps = shared subtree params (this quarter), pk = shared class offsets (this quarter).
template <int ld, int j>
struct Walk {
    static __device__ __forceinline__ void run(float Na, float Da, float Nb, float Db,
                                               const char* xb, char* sb,
                                               const float2* ps, const uint32_t* pk) {
        float2 p  = ps[(1 << ld) - 1 + j];
        float2 xv = lds2(xb + __float_as_int(p.y));
        float ea = ex2f(fmaf(xv.x, LOG2E, p.x));
        float eb = ex2f(fmaf(xv.y, LOG2E, p.x));
        float Dna = fmaf(Da, ea, Da);      // D*(1+e)
        float Dnb = fmaf(Db, eb, Db);
        Walk<ld + 1, 2 * j>::run(Na, Dna, Nb, Dnb, xb, sb, ps, pk);
        Walk<ld + 1, 2 * j + 1>::run(Na * ea, Dna, Nb * eb, Dnb, xb, sb, ps, pk);
    }
};

// Depth-6 handler: evaluates its node plus BOTH depth-7 children, sharing one
// rcp per sample across the two children: r=rcp(DL*DR); 1/DL=r*DR; 1/DR=r*DL.
template <int j>
struct Walk<4, j> {
    static __device__ __forceinline__ void run(float Na, float Da, float Nb, float Db,
                                               const char* xb, char* sb,
                                               const float2* ps, const uint32_t* pk) {
        // depth-6 node
        float2 p  = ps[15 + j];
        float2 xv = lds2(xb + __float_as_int(p.y));
        float e6a = ex2f(fmaf(xv.x, LOG2E, p.x));
        float e6b = ex2f(fmaf(xv.y, LOG2E, p.x));
        float D6a = fmaf(Da, e6a, Da);
        float D6b = fmaf(Db, e6b, Db);
        float NRa = Na * e6a;              // right-child numerators
        float NRb = Nb * e6b;

        // left depth-7 child
        float2 pL  = ps[31 + 2 * j];
        float2 xL  = lds2(xb + __float_as_int(pL.y));
        float eLa = ex2f(fmaf(xL.x, LOG2E, pL.x));
        float eLb = ex2f(fmaf(xL.y, LOG2E, pL.x));
        float DLa = fmaf(D6a, eLa, D6a);
        float DLb = fmaf(D6b, eLb, D6b);

        // right depth-7 child
        float2 pR  = ps[32 + 2 * j];
        float2 xR  = lds2(xb + __float_as_int(pR.y));
        float eRa = ex2f(fmaf(xR.x, LOG2E, pR.x));
        float eRb = ex2f(fmaf(xR.y, LOG2E, pR.x));
        float DRa = fmaf(D6a, eRa, D6a);
        float DRb = fmaf(D6b, eRb, D6b);

        // combined reciprocal (one rcp per sample for both children)
        float ra  = rcpf(DLa * DRa);
        float rb  = rcpf(DLb * DRb);
        float iLa = ra * DRa, iRa = ra * DLa;
        float iLb = rb * DRb, iRb = rb * DLb;

        // leaves under left d7 child
        float PLLa = Na * iLa,   PLLb = Nb * iLb;
        float PLRa = PLLa * eLa, PLRb = PLLb * eLb;
        uint32_t k0 = pk[2 * j];
        {
            float2* aL = (float2*)(sb + (k0 & 0xFFFFu));
            float2* aR = (float2*)(sb + (k0 >> 16));
            float2 vL = *aL; vL.x += PLLa; vL.y += PLLb; *aL = vL;
            float2 vR = *aR; vR.x += PLRa; vR.y += PLRb; *aR = vR;
        }
        // leaves under right d7 child
        float PRLa = NRa * iRa,  PRLb = NRb * iRb;
        float PRRa = PRLa * eRa, PRRb = PRLb * eRb;
        uint32_t k1 = pk[2 * j + 1];
        {
            float2* aL = (float2*)(sb + (k1 & 0xFFFFu));
            float2* aR = (float2*)(sb + (k1 >> 16));
            float2 vL = *aL; vL.x += PRLa; vL.y += PRLb; *aL = vL;
            float2 vR = *aR; vR.x += PRRa; vR.y += PRRb; *aR = vR;
        }
    }
};

__global__ void __launch_bounds__(BT, 4)
dt_kernel(const float* __restrict__ x,
          const float* __restrict__ thr,
          const int*   __restrict__ feats,
          const int*   __restrict__ cls,
          float* __restrict__ out) {
    __shared__ __align__(16) float    xs[N_FEAT * PADF];      // 16.6 KB
    __shared__ __align__(16) float    sacc[4 * N_CLS * SPB];  // 20 KB
    __shared__ __align__(8)  float2   s_top[3];
    __shared__ __align__(8)  float2   s_ps[4 * N_SUB];        // 2.0 KB
    __shared__               uint32_t s_pk[128];              // 0.5 KB

    const int tid = threadIdx.x;
    const int bs  = blockIdx.x * SPB;
    const int q   = tid >> 6;              // quarter (warp-uniform)
    const int pr  = tid & (NPAIR - 1);     // sample-pair index

    // ---- per-block param prep (replaces prep kernel + constant memcpys) ----
    if (tid < 3) {
        s_top[tid] = make_float2(-thr[tid] * LOG2E, __int_as_float(feats[tid] * PADF * 4));
    }
    if (tid < 4 * N_SUB) {
        int qq  = tid / N_SUB;
        int rem = tid - qq * N_SUB;        // 0..62, level order within subtree
        int ld  = 31 - __clz(rem + 1);     // 0..5
        int j   = rem + 1 - (1 << ld);
        int g   = ((1 << (ld + 2)) - 1) + qq * (1 << ld) + j;
        s_ps[tid] = make_float2(-thr[g] * LOG2E, __int_as_float(feats[g] * PADF * 4));
    }
    if (tid < 128) {                       // depth-7 in-level index
        uint32_t offL = (uint32_t)cls[2 * tid]     * (SPB * 4);
        uint32_t offR = (uint32_t)cls[2 * tid + 1] * (SPB * 4);
        s_pk[tid] = offL | (offR << 16);
    }

    // ---- stage 128 samples x 32 feats, coalesced LDG.128 ----
#pragma unroll
    for (int k = 0; k < (SPB * N_FEAT / 4) / BT; k++) {
        int idx = tid + k * BT;
        int s   = idx >> 3;
        int c4  = idx & 7;
        float4 v = reinterpret_cast<const float4*>(x + (size_t)(bs + s) * N_FEAT)[c4];
        xs[(c4 * 4 + 0) * PADF + s] = v.x;
        xs[(c4 * 4 + 1) * PADF + s] = v.y;
        xs[(c4 * 4 + 2) * PADF + s] = v.z;
        xs[(c4 * 4 + 3) * PADF + s] = v.w;
    }

    char* sb = (char*)sacc + q * (N_CLS * SPB * 4) + 8 * pr;
#pragma unroll
    for (int c = 0; c < N_CLS; c++)
        *(float2*)(sb + c * (SPB * 4)) = make_float2(0.f, 0.f);

    __syncthreads();

    const char* xb = (const char*)xs + 8 * pr;
    const float2*   ps = s_ps + q * N_SUB;
    const uint32_t* pk = s_pk + q * 32;

    // replicated top 2 levels
    float2 p0  = s_top[0];
    float2 xv0 = lds2(xb + __float_as_int(p0.y));
    float e0a = ex2f(fmaf(xv0.x, LOG2E, p0.x));
    float e0b = ex2f(fmaf(xv0.y, LOG2E, p0.x));
    float Da = e0a + 1.f;
    float Db = e0b + 1.f;
    float Na = (q & 2) ? e0a : 1.0f;
    float Nb = (q & 2) ? e0b : 1.0f;

    float2 p1  = s_top[1 + (q >> 1)];
    float2 xv1 = lds2(xb + __float_as_int(p1.y));
    float e1a = ex2f(fmaf(xv1.x, LOG2E, p1.x));
    float e1b = ex2f(fmaf(xv1.y, LOG2E, p1.x));
    Da = fmaf(Da, e1a, Da);
    Db = fmaf(Db, e1b, Db);
    if (q & 1) { Na *= e1a; Nb *= e1b; }

    Walk<0, 0>::run(Na, Da, Nb, Db, xb, sb, ps, pk);

    __syncthreads();

    // combine 4 quarter-accumulators, write out
    if (tid < SPB) {
        float a[N_CLS];
#pragma unroll
        for (int c = 0; c < N_CLS; c++) {
            float v = 0.f;
#pragma unroll
            for (int qq = 0; qq < 4; qq++)
                v += sacc[qq * (N_CLS * SPB) + c * SPB + tid];
            a[c] = v;
        }
        float* o = out + (size_t)(bs + tid) * N_CLS;
#pragma unroll
        for (int c = 0; c < N_CLS; c += 2)
            *(float2*)(o + c) = make_float2(a[c], a[c + 1]);
    }
}

extern "C" void kernel_launch(void* const* d_in, const int* in_sizes, int n_in,
                              void* d_out, int out_size) {
    const float* x     = (const float*)d_in[0];
    const float* thr   = (const float*)d_in[1];
    const int*   feats = (const int*)d_in[2];
    const int*   cls   = (const int*)d_in[3];
    float*       out   = (float*)d_out;

    const int B = in_sizes[0] / N_FEAT;

    dt_kernel<<<B / SPB, BT>>>(x, thr, feats, cls, out);
}